// round 16
// baseline (speedup 1.0000x reference)
#include <cuda_runtime.h>
#include <cuda_bf16.h>
#include <cuda_fp16.h>
#include <cstdint>

#define BB 32
#define NNODE 1024
#define CCH 64
#define TTT 24
#define CT 1536      // C*T == O*T == FT*T
#define K_GCN 3072   // plain fp16, K over (k,m)
#define K_SG  1024   // plain fp16, K over m

// ---------------- scratch (device globals; allocation-free) ----------------
__device__ float g_lhs1[BB*TTT*CCH];
__device__ float g_lhs2[BB*TTT*NNODE];
__device__ float g_rhsT[BB*NNODE*TTT];
__device__ float g_prodT[BB*TTT*TTT];
__device__ float g_tAt[BB*TTT*TTT];
__device__ float g_lhsB[BB*NNODE*TTT];
__device__ float g_rhsA[BB*NNODE*TTT];
__device__ float g_S[(size_t)BB*NNODE*NNODE];
__device__ __align__(16) uint32_t g_gcnH[(size_t)BB*NNODE*CT/2];    // half2 pairs
__device__ __align__(16) __half   g_Zh[(size_t)BB*K_GCN*CT];        // [b,km,ot] fp16
__device__ __align__(16) __half   g_AhT[(size_t)BB*K_GCN*NNODE];    // [b,km,n] fp16
__device__ __align__(16) uint32_t g_sigH[(size_t)BB*NNODE*(K_SG/2)]; // [b,n,m/2]
__device__ __align__(16) uint32_t g_VsH[(size_t)NNODE*(K_SG/2)];     // [m,k/2]

// ---------------- PTX helpers ----------------
__device__ __forceinline__ void cpa16(uint32_t dst, const void* src){
    asm volatile("cp.async.cg.shared.global [%0], [%1], 16;\n" :: "r"(dst), "l"(src));
}
__device__ __forceinline__ void cpa_commit(){ asm volatile("cp.async.commit_group;\n"); }
__device__ __forceinline__ void cpa_wait0(){ asm volatile("cp.async.wait_group 0;\n"); }
__device__ __forceinline__ void ldsm4(uint32_t* r, uint32_t addr){
    asm volatile("ldmatrix.sync.aligned.m8n8.x4.shared.b16 {%0,%1,%2,%3},[%4];"
        : "=r"(r[0]),"=r"(r[1]),"=r"(r[2]),"=r"(r[3]) : "r"(addr));
}
__device__ __forceinline__ void ldsm4t(uint32_t* r, uint32_t addr){
    asm volatile("ldmatrix.sync.aligned.m8n8.x4.trans.shared.b16 {%0,%1,%2,%3},[%4];"
        : "=r"(r[0]),"=r"(r[1]),"=r"(r[2]),"=r"(r[3]) : "r"(addr));
}
__device__ __forceinline__ void mma16816(float* c, const uint32_t* a, const uint32_t* b){
    asm volatile("mma.sync.aligned.m16n8k16.row.col.f32.f16.f16.f32 "
        "{%0,%1,%2,%3}, {%4,%5,%6,%7}, {%8,%9}, {%0,%1,%2,%3};"
        : "+f"(c[0]),"+f"(c[1]),"+f"(c[2]),"+f"(c[3])
        : "r"(a[0]),"r"(a[1]),"r"(a[2]),"r"(a[3]), "r"(b[0]),"r"(b[1]));
}
__device__ __forceinline__ uint32_t pack_ff(float a, float b){
    __half2 h = __floats2half2_rn(a, b);
    return *(uint32_t*)&h;
}

// ---------------- 1a: lhs1[b,t,c] = sum_n x[b,n,c,t]*U1[n] ----------------
__global__ void k_lhs1(const float* __restrict__ x, const float* __restrict__ U1){
    int b = blockIdx.x, c = blockIdx.y;
    int t = threadIdx.x % 24, r = threadIdx.x / 24;   // r in 0..7, blockDim 192
    float acc = 0.f;
    for(int n = r; n < NNODE; n += 8)
        acc += x[(((size_t)b*NNODE+n)*CCH+c)*TTT+t] * __ldg(U1+n);
    __shared__ float s[8][24];
    s[r][t] = acc;
    __syncthreads();
    if(r == 0){
        float v = 0.f;
        #pragma unroll
        for(int i = 0; i < 8; i++) v += s[i][t];
        g_lhs1[(b*TTT+t)*CCH+c] = v;
    }
}

// ---------------- 1c': rhsT[b,n,t] = sum_c U3[c]*x[b,n,c,t] ----------------
__global__ void k_rhsT(const float* __restrict__ x, const float* __restrict__ U3){
    int idx = blockIdx.x*8 + (threadIdx.x>>5);   // b*N+n
    int t = threadIdx.x & 31;
    if(t >= 24) return;
    size_t base = (size_t)idx*CT;
    float acc = 0.f;
    #pragma unroll
    for(int c = 0; c < CCH; c++) acc += __ldg(U3+c) * x[base + c*TTT + t];
    g_rhsT[idx*TTT + t] = acc;
}

// ---------------- 1b: lhs2[b,t,n] = sum_c lhs1[b,t,c]*U2[c,n] --------------
__global__ void k_lhs2(const float* __restrict__ U2){
    int bt = blockIdx.x;
    __shared__ float l[CCH];
    if(threadIdx.x < CCH) l[threadIdx.x] = g_lhs1[bt*CCH + threadIdx.x];
    __syncthreads();
    for(int n = threadIdx.x; n < NNODE; n += 256){
        float a = 0.f;
        #pragma unroll
        for(int c = 0; c < CCH; c++) a += l[c]*U2[c*NNODE + n];
        g_lhs2[bt*NNODE + n] = a;
    }
}

// ---------------- 1c: prodT[b,s,t] = sum_n lhs2[b,s,n]*rhsT[b,n,t] ---------
__global__ void k_prodT(){
    int b = blockIdx.x;
    int s = threadIdx.x / 24, t = threadIdx.x % 24;  // blockDim 576
    __shared__ float A[24][96], Bm[96][24];
    float acc = 0.f;
    for(int n0 = 0; n0 < NNODE; n0 += 96){
        __syncthreads();
        for(int i = threadIdx.x; i < 24*96; i += 576){
            int row = i/96, col = i%96;
            A[row][col] = g_lhs2[(b*TTT+row)*NNODE + n0 + col];
            int rr = i/24, cc = i%24;
            Bm[rr][cc] = g_rhsT[((size_t)b*NNODE + n0 + rr)*TTT + cc];
        }
        __syncthreads();
        #pragma unroll
        for(int j = 0; j < 96; j++) acc += A[s][j]*Bm[j][t];
    }
    g_prodT[(b*TTT+s)*TTT+t] = acc;
}

// ---------------- 1d: E = Ve @ sigmoid(prodT + be); softmax over axis s ----
__global__ void k_tAt(const float* __restrict__ be, const float* __restrict__ Ve){
    int b = blockIdx.x;
    int s = threadIdx.x / 24, y = threadIdx.x % 24;  // blockDim 576
    __shared__ float sig[24][24], E[24][25];
    __shared__ float mx[24], sm[24];
    float v = g_prodT[(b*TTT+s)*TTT+y] + __ldg(be + s*TTT + y);
    sig[s][y] = 1.f/(1.f + expf(-v));
    __syncthreads();
    float acc = 0.f;
    #pragma unroll
    for(int t = 0; t < 24; t++) acc += __ldg(Ve + s*TTT + t)*sig[t][y];
    E[s][y] = acc;
    __syncthreads();
    if(s == 0){
        float m = -1e30f;
        #pragma unroll
        for(int i = 0; i < 24; i++) m = fmaxf(m, E[i][y]);
        float ss = 0.f;
        #pragma unroll
        for(int i = 0; i < 24; i++) ss += expf(E[i][y]-m);
        mx[y] = m; sm[y] = ss;
    }
    __syncthreads();
    g_tAt[(b*TTT+s)*TTT+y] = expf(E[s][y]-mx[y])/sm[y];
}

// ---- 4 (independent of attention): Zh[b,km,ot] = fp16(sum_c x·Theta) ------
__global__ void k_Z(const float* __restrict__ x, const float* __restrict__ Theta){
    size_t bm = blockIdx.x;
    int b = (int)(bm >> 10), m = (int)(bm & 1023);
    __shared__ float xs[1536];
    for(int i = threadIdx.x; i < 1536; i += 192) xs[i] = x[bm*CT + i];
    __syncthreads();
    int k = threadIdx.x >> 6, o = threadIdx.x & 63;   // blockDim 192
    float acc[24];
    #pragma unroll
    for(int t = 0; t < 24; t++) acc[t] = 0.f;
    const float* th = Theta + k*4096 + o;
    #pragma unroll 4
    for(int c = 0; c < 64; c++){
        float w = __ldg(th + c*64);
        const float* xr = xs + c*24;
        #pragma unroll
        for(int t = 0; t < 24; t++) acc[t] += w*xr[t];
    }
    uint32_t* zp = (uint32_t*)(g_Zh + (((size_t)(b*3 + k)<<10) + m)*CT) + o*12;
    #pragma unroll
    for(int j = 0; j < 12; j++)
        zp[j] = pack_ff(acc[2*j], acc[2*j+1]);
}

// ------------- MEGA2: per (b,n) — x_TAt, lhsB, rhsA ------------------------
__global__ void __launch_bounds__(256) k_mega2(
        const float* __restrict__ x,
        const float* __restrict__ W1, const float* __restrict__ W2,
        const float* __restrict__ W3){
    extern __shared__ float sm[];
    float* a = sm;                        // 576: tAt[b]
    float* base = sm + 576;
    int grp = threadIdx.x >> 6, c = threadIdx.x & 63;  // 4 groups x 64
    float* xs  = base + grp*3136;         // 1536
    float* buf = xs + 1536;               // 64 x 25
    size_t bn = (size_t)blockIdx.x*4 + grp;
    int b = (int)(bn >> 10);

    for(int i = threadIdx.x; i < 576; i += 256) a[i] = g_tAt[b*576 + i];
    for(int i = c; i < 1536; i += 64) xs[i] = x[bn*CT + i];
    __syncthreads();

    // --- x_TAt row c: acc[s] = sum_t xs[c,t]*a[t,s] ---
    float acc[24];
    #pragma unroll
    for(int s = 0; s < 24; s++) acc[s] = 0.f;
    const float* xr = xs + c*24;
    #pragma unroll 4
    for(int t = 0; t < 24; t++){
        float xv = xr[t];
        const float* ar = a + t*24;
        #pragma unroll
        for(int s = 0; s < 24; s++) acc[s] += xv*ar[s];
    }
    float la = 0.f;
    #pragma unroll
    for(int t = 0; t < 24; t++) la += acc[t]*__ldg(W1+t);

    // --- rhsA[t] = sum_c W3[c]*acc[c][t] ---
    float w3 = __ldg(W3 + c);
    #pragma unroll
    for(int t = 0; t < 24; t++) buf[c*25 + t] = w3*acc[t];
    __syncthreads();
    if(c < 24){
        float r = 0.f;
        #pragma unroll 8
        for(int c2 = 0; c2 < 64; c2++) r += buf[c2*25 + c];
        g_rhsA[bn*TTT + c] = r;
    }
    __syncthreads();
    // --- lhsB[t] = sum_c la[c]*W2[c,t] ---
    #pragma unroll
    for(int t = 0; t < 24; t++) buf[c*25 + t] = la*__ldg(W2 + c*24 + t);
    __syncthreads();
    if(c < 24){
        float r = 0.f;
        #pragma unroll 8
        for(int c2 = 0; c2 < 64; c2++) r += buf[c2*25 + c];
        g_lhsB[bn*TTT + c] = r;
    }
}

// ----- 3d: sigH[b,n,m] = fp16 of sigmoid(lhsB·rhsAᵀ + bs) ------------------
__global__ void k_prodS(const float* __restrict__ bs){
    int b = blockIdx.z;
    int m0 = blockIdx.y*32, n0 = blockIdx.x*32;
    __shared__ float Am[32][25], Bn[32][25];
    __shared__ float st[32][33];   // [n local][m local]
    for(int i = threadIdx.x; i < 32*24; i += 256){
        int r = i/24, cc = i%24;
        Am[r][cc] = g_lhsB[((size_t)b*NNODE + m0 + r)*TTT + cc];
        Bn[r][cc] = g_rhsA[((size_t)b*NNODE + n0 + r)*TTT + cc];
    }
    __syncthreads();
    int tm = threadIdx.x >> 5, tn = threadIdx.x & 31;
    #pragma unroll
    for(int r = 0; r < 4; r++){
        int m = tm*4 + r;
        float acc = 0.f;
        #pragma unroll
        for(int t = 0; t < 24; t++) acc += Am[m][t]*Bn[tn][t];
        float v = acc + __ldg(bs + (size_t)(m0+m)*NNODE + n0 + tn);
        st[tn][m] = 1.f/(1.f + expf(-v));
    }
    __syncthreads();
    int nl = threadIdx.x >> 3, kq = (threadIdx.x & 7)*4;
    uint32_t* dst = g_sigH + ((size_t)(b*NNODE + n0 + nl))*(K_SG/2) + ((m0 + kq)>>1);
    uint2 w;
    w.x = pack_ff(st[nl][kq+0], st[nl][kq+1]);
    w.y = pack_ff(st[nl][kq+2], st[nl][kq+3]);
    *(uint2*)dst = w;
}

// ---------------- prep: VsH[m,k] = fp16 of Vs[m,k] -------------------------
__global__ void k_prepVs(const float* __restrict__ Vs){
    int m = blockIdx.x;
    for(int k2 = threadIdx.x; k2 < K_SG/2; k2 += 256){
        float v0 = Vs[(size_t)m*NNODE + 2*k2];
        float v1 = Vs[(size_t)m*NNODE + 2*k2 + 1];
        g_VsH[(size_t)m*(K_SG/2) + k2] = pack_ff(v0, v1);
    }
}

// ---------------- 3f: softmax over m of S (in place -> spatial_At) ---------
__global__ void k_softS(){
    int b = blockIdx.y;
    int ly = threadIdx.x & 63;
    int y = blockIdx.x*64 + ly;
    int tg = threadIdx.x >> 6;
    __shared__ float red[4][64];
    float* col = g_S + ((size_t)b<<20) + y;
    float m = -1e30f;
    for(int mm = tg; mm < NNODE; mm += 4) m = fmaxf(m, col[(size_t)mm*NNODE]);
    red[tg][ly] = m;
    __syncthreads();
    m = fmaxf(fmaxf(red[0][ly], red[1][ly]), fmaxf(red[2][ly], red[3][ly]));
    float s = 0.f;
    for(int mm = tg; mm < NNODE; mm += 4) s += expf(col[(size_t)mm*NNODE] - m);
    __syncthreads();
    red[tg][ly] = s;
    __syncthreads();
    s = red[0][ly] + red[1][ly] + red[2][ly] + red[3][ly];
    float inv = 1.f/s;
    for(int mm = tg; mm < NNODE; mm += 4){
        float v = col[(size_t)mm*NNODE];
        col[(size_t)mm*NNODE] = expf(v - m)*inv;
    }
}

// ----- prep A (streaming): AhT[b,km,n] = fp16(cheb[km,n]*At[b,m,n]) --------
__global__ void __launch_bounds__(256) k_prepA(const float* __restrict__ cheb){
    int b = blockIdx.z;
    int km = blockIdx.y*32 + (threadIdx.x>>3);
    int n  = blockIdx.x*256 + (threadIdx.x&7)*32;
    int m  = km & 1023;
    const float* cb = cheb + (size_t)km*NNODE + n;
    const float* sp = g_S + ((size_t)b<<20) + ((size_t)m<<10) + n;
    uint32_t* dst = (uint32_t*)(g_AhT + ((size_t)(b*3072) + km)*NNODE + n);
    #pragma unroll
    for(int i = 0; i < 16; i++)
        dst[i] = pack_ff(cb[2*i]*sp[2*i], cb[2*i+1]*sp[2*i+1]);
}

// ----- trans-operand mma GEMM: C[128,128] = Aᵀ-panel · B-panel -------------
// A: [KP rows][ldA halves] (cols = M), B: [KP rows][ldB halves] (cols = N).
// fp16 operands, fp32 accum, fused ReLU, half2-packed C (ldC in half2 units).
__global__ void __launch_bounds__(256,2) k_gcnMMA(){
    int b = blockIdx.z;
    const __half* A = g_AhT + (size_t)b*K_GCN*NNODE;
    const __half* B = g_Zh  + (size_t)b*K_GCN*CT;
    uint32_t* C = g_gcnH + (size_t)b*NNODE*(CT/2);
    const int ldA = NNODE, ldB = CT, ldC = CT/2, KP = K_GCN;

    extern __shared__ uint16_t sh[];   // A[2][64][128] then B[2][64][128]
    int m0 = blockIdx.y*128, n0 = blockIdx.x*128;
    int tid = threadIdx.x, wid = tid>>5, lane = tid&31;
    int wm = (wid>>1)*32, wn = (wid&1)*64;
    uint32_t sA0 = (uint32_t)__cvta_generic_to_shared(sh);
    uint32_t sB0 = sA0 + 2*16384;

    float acc[2][8][4];
    #pragma unroll
    for(int mi = 0; mi < 2; mi++)
        #pragma unroll
        for(int ni = 0; ni < 8; ni++)
            #pragma unroll
            for(int q = 0; q < 4; q++) acc[mi][ni][q] = 0.f;

    auto loadStage = [&](int buf, int k0){
        #pragma unroll
        for(int i = 0; i < 4; i++){
            int idx = tid + i*256;
            int row = idx>>4, g = idx&15;
            int pg = g ^ (row & 7);
            cpa16(sA0 + (uint32_t)(buf*16384 + row*256 + pg*16),
                  A + (size_t)(k0+row)*ldA + m0 + g*8);
            cpa16(sB0 + (uint32_t)(buf*16384 + row*256 + pg*16),
                  B + (size_t)(k0+row)*ldB + n0 + g*8);
        }
        cpa_commit();
    };

    int ns = KP/64;
    loadStage(0, 0);
    cpa_wait0();
    __syncthreads();
    int gA_ = lane>>3;
    int mbA = gA_ & 1, khA = gA_ >> 1;       // A mats: mb = g&1, kh = g>>1
    int khB = gA_ & 1, nbB = gA_ >> 1;       // B mats: kh = g&1, nb = g>>1
    for(int s = 0; s < ns; s++){
        int buf = s & 1;
        if(s + 1 < ns) loadStage(buf^1, (s+1)*64);
        uint32_t baseA = sA0 + buf*16384;
        uint32_t baseB = sB0 + buf*16384;
        #pragma unroll
        for(int j = 0; j < 4; j++){
            uint32_t a[2][4];
            int rowA = (2*j + khA)*8 + (lane & 7);
            #pragma unroll
            for(int mi = 0; mi < 2; mi++){
                int gcol = (wm + mi*16 + mbA*8) >> 3;
                ldsm4t(a[mi], baseA + (uint32_t)(rowA*256 + ((gcol ^ (rowA&7))*16)));
            }
            uint32_t bb[4][4];
            int rowB = (2*j + khB)*8 + (lane & 7);
            #pragma unroll
            for(int p = 0; p < 4; p++){
                int gcol = (wn + p*16 + nbB*8) >> 3;
                ldsm4t(bb[p], baseB + (uint32_t)(rowB*256 + ((gcol ^ (rowB&7))*16)));
            }
            #pragma unroll
            for(int mi = 0; mi < 2; mi++)
                #pragma unroll
                for(int ni = 0; ni < 8; ni++)
                    mma16816(acc[mi][ni], a[mi], &bb[ni>>1][(ni&1)*2]);
        }
        if(s + 1 < ns) cpa_wait0();
        __syncthreads();
    }

    int r0 = m0 + wm + (lane >> 2);
    int c0 = n0 + wn + (lane & 3)*2;
    #pragma unroll
    for(int mi = 0; mi < 2; mi++){
        #pragma unroll
        for(int ni = 0; ni < 8; ni++){
            float v0 = fmaxf(acc[mi][ni][0],0.f), v1 = fmaxf(acc[mi][ni][1],0.f);
            float v2 = fmaxf(acc[mi][ni][2],0.f), v3 = fmaxf(acc[mi][ni][3],0.f);
            int r = r0 + mi*16, c = c0 + ni*8;
            C[(size_t)r*ldC + (c>>1)]     = pack_ff(v0, v1);
            C[(size_t)(r+8)*ldC + (c>>1)] = pack_ff(v2, v3);
        }
    }
}

// ---------------- mma GEMM (row-major [N,K] B), for Sgemm ------------------
__global__ void __launch_bounds__(256,2) k_SgemmMMA(){
    int b = blockIdx.z;
    const uint16_t* A = (const uint16_t*)g_VsH;
    const uint16_t* B = (const uint16_t*)(g_sigH + (size_t)b*NNODE*(K_SG/2));
    float* C = g_S + ((size_t)b<<20);
    const int ldC = NNODE, KP = K_SG;

    extern __shared__ uint16_t sh[];
    int m0 = blockIdx.y*128, n0 = blockIdx.x*128;
    const uint16_t* gA = A + (size_t)m0*KP;
    const uint16_t* gB = B + (size_t)n0*KP;
    int tid = threadIdx.x, wid = tid>>5, lane = tid&31;
    int wm = (wid>>1)*32, wn = (wid&1)*64;
    uint32_t sA0 = (uint32_t)__cvta_generic_to_shared(sh);
    uint32_t sB0 = sA0 + 2*16384;

    float acc[2][8][4];
    #pragma unroll
    for(int mi = 0; mi < 2; mi++)
        #pragma unroll
        for(int ni = 0; ni < 8; ni++)
            #pragma unroll
            for(int q = 0; q < 4; q++) acc[mi][ni][q] = 0.f;

    auto loadStage = [&](int buf, int k0){
        #pragma unroll
        for(int i = 0; i < 4; i++){
            int idx = tid + i*256;
            int row = idx>>3, cc = idx&7;
            int pc = (cc ^ (row & 7));
            cpa16(sA0 + (uint32_t)(buf*16384 + (row*64 + pc*8)*2),
                  gA + (size_t)row*KP + k0 + cc*8);
            cpa16(sB0 + (uint32_t)(buf*16384 + (row*64 + pc*8)*2),
                  gB + (size_t)row*KP + k0 + cc*8);
        }
        cpa_commit();
    };

    int ns = KP/64;
    loadStage(0, 0);
    cpa_wait0();
    __syncthreads();
    for(int s = 0; s < ns; s++){
        int buf = s & 1;
        if(s + 1 < ns) loadStage(buf^1, (s+1)*64);
        uint32_t baseA = sA0 + buf*16384;
        uint32_t baseB = sB0 + buf*16384;
        #pragma unroll
        for(int j = 0; j < 4; j++){
            uint32_t a[2][4];
            int arow = wm + (lane & 15);
            int acc_ = 2*j + (lane >> 4);
            #pragma unroll
            for(int mi = 0; mi < 2; mi++){
                int r = arow + mi*16;
                ldsm4(a[mi], baseA + (uint32_t)((r*64 + ((acc_ ^ (r&7))*8))*2));
            }
            uint32_t bb[4][4];
            int brow = wn + (lane & 7) + ((lane >> 4) << 3);
            int bcc = 2*j + ((lane >> 3) & 1);
            #pragma unroll
            for(int p = 0; p < 4; p++){
                int r = brow + p*16;
                ldsm4(bb[p], baseB + (uint32_t)((r*64 + ((bcc ^ (r&7))*8))*2));
            }
            #pragma unroll
            for(int mi = 0; mi < 2; mi++)
                #pragma unroll
                for(int ni = 0; ni < 8; ni++)
                    mma16816(acc[mi][ni], a[mi], &bb[ni>>1][(ni&1)*2]);
        }
        if(s + 1 < ns) cpa_wait0();
        __syncthreads();
    }

    int r0 = m0 + wm + (lane >> 2);
    int c0 = n0 + wn + (lane & 3)*2;
    #pragma unroll
    for(int mi = 0; mi < 2; mi++){
        #pragma unroll
        for(int ni = 0; ni < 8; ni++){
            int r = r0 + mi*16, c = c0 + ni*8;
            float2 w0; w0.x = acc[mi][ni][0]; w0.y = acc[mi][ni][1];
            float2 w1; w1.x = acc[mi][ni][2]; w1.y = acc[mi][ni][3];
            *(float2*)(C + (size_t)r*ldC + c)     = w0;
            *(float2*)(C + (size_t)(r+8)*ldC + c) = w1;
        }
    }
}

// ------- 6: tconv + rconv + relu + LN(ft) + transpose -> out ---------------
__global__ void k_final(const float* __restrict__ x,
                        const float* __restrict__ twg, const float* __restrict__ tbg,
                        const float* __restrict__ rwg, const float* __restrict__ rbg,
                        const float* __restrict__ lng, const float* __restrict__ lnb,
                        float* __restrict__ out){
    extern __shared__ float smdyn[];
    int grp = threadIdx.x >> 6;           // blockDim 256 = 4 groups x 64
    int ft  = threadIdx.x & 63;
    size_t bn = (size_t)blockIdx.x*4 + grp;
    float* xs = smdyn + grp*4632;
    float* gs = xs + 1536;
    float* ys = gs + 1536;                // stride 65 per t: 24*65 = 1560
    __shared__ float s_mu[4][24], s_rs[4][24];
    for(int i = ft; i < 1536; i += 64) xs[i] = x[bn*CT + i];
    const uint32_t* gh = g_gcnH + bn*(CT/2);
    for(int ii = ft; ii < CT/2; ii += 64){
        uint32_t u = gh[ii];
        __half2 h = *(__half2*)&u;
        float2 f = __half22float2(h);
        gs[ii*2]   = f.x;
        gs[ii*2+1] = f.y;
    }
    __syncthreads();
    float acc[24];
    float bias = __ldg(tbg+ft) + __ldg(rbg+ft);
    #pragma unroll
    for(int t = 0; t < 24; t++) acc[t] = bias;
    const float* rwr = rwg + ft*64;
    #pragma unroll 4
    for(int c = 0; c < 64; c++){
        float w = __ldg(rwr + c);
        const float* xr = xs + c*24;
        #pragma unroll
        for(int t = 0; t < 24; t++) acc[t] += w*xr[t];
    }
    const float* twr = twg + ft*192;
    #pragma unroll 2
    for(int o = 0; o < 64; o++){
        float w0 = __ldg(twr + o*3), w1 = __ldg(twr + o*3 + 1), w2 = __ldg(twr + o*3 + 2);
        const float* gr = gs + o*24;
        #pragma unroll
        for(int t = 0; t < 24; t++){
            float s = w1*gr[t];
            if(t > 0)  s += w0*gr[t-1];
            if(t < 23) s += w2*gr[t+1];
            acc[t] += s;
        }
    }
    #pragma unroll
    for(int t = 0; t < 24; t++) ys[t*65 + ft] = fmaxf(acc[t], 0.f);
    __syncthreads();
    int lane = threadIdx.x & 31;
    int wg = ft >> 5;
    for(int t = wg; t < 24; t += 2){
        float v1 = ys[t*65 + lane], v2 = ys[t*65 + 32 + lane];
        float s = v1 + v2, q = v1*v1 + v2*v2;
        #pragma unroll
        for(int off = 16; off; off >>= 1){
            s += __shfl_xor_sync(0xffffffffu, s, off);
            q += __shfl_xor_sync(0xffffffffu, q, off);
        }
        if(lane == 0){
            float mean = s*(1.f/64.f);
            s_mu[grp][t] = mean;
            s_rs[grp][t] = rsqrtf(q*(1.f/64.f) - mean*mean + 1e-5f);
        }
    }
    __syncthreads();
    float gg = __ldg(lng+ft), bv = __ldg(lnb+ft);
    #pragma unroll
    for(int t = 0; t < 24; t++)
        ys[t*65 + ft] = (ys[t*65 + ft] - s_mu[grp][t])*s_rs[grp][t]*gg + bv;
    __syncthreads();
    for(int i = ft; i < 1536; i += 64)
        out[bn*CT + i] = ys[(i%24)*65 + (i/24)];
}

// ---------------------------------------------------------------------------
extern "C" void kernel_launch(void* const* d_in, const int* in_sizes, int n_in,
                              void* d_out, int out_size){
    const float* x   = (const float*)d_in[0];
    const float* W1  = (const float*)d_in[1];
    const float* W2  = (const float*)d_in[2];
    const float* W3  = (const float*)d_in[3];
    const float* bs  = (const float*)d_in[4];
    const float* Vs  = (const float*)d_in[5];
    const float* U1  = (const float*)d_in[6];
    const float* U2  = (const float*)d_in[7];
    const float* U3  = (const float*)d_in[8];
    const float* be  = (const float*)d_in[9];
    const float* Ve  = (const float*)d_in[10];
    const float* Th  = (const float*)d_in[11];
    const float* cheb= (const float*)d_in[12];
    const float* tw  = (const float*)d_in[13];
    const float* tb  = (const float*)d_in[14];
    const float* rw  = (const float*)d_in[15];
    const float* rb  = (const float*)d_in[16];
    const float* lg  = (const float*)d_in[17];
    const float* lb  = (const float*)d_in[18];
    float* out = (float*)d_out;

    // one-time host-side setup (streams/events are host resources, no device mem)
    static cudaStream_t s1 = nullptr;
    static cudaEvent_t evFork = nullptr, evJoin = nullptr;
    if(s1 == nullptr){
        cudaStreamCreateWithFlags(&s1, cudaStreamNonBlocking);
        cudaEventCreateWithFlags(&evFork, cudaEventDisableTiming);
        cudaEventCreateWithFlags(&evJoin, cudaEventDisableTiming);
    }

    const int MEGA_SMEM = (576 + 4*3136)*4;   // 52480 B
    cudaFuncSetAttribute(k_final, cudaFuncAttributeMaxDynamicSharedMemorySize, 4*4632*4);
    cudaFuncSetAttribute(k_mega2, cudaFuncAttributeMaxDynamicSharedMemorySize, MEGA_SMEM);
    cudaFuncSetAttribute(k_SgemmMMA, cudaFuncAttributeMaxDynamicSharedMemorySize, 65536);
    cudaFuncSetAttribute(k_gcnMMA,   cudaFuncAttributeMaxDynamicSharedMemorySize, 65536);

    // ---- fork side stream: Z (independent of attention) ----
    cudaEventRecord(evFork, 0);
    cudaStreamWaitEvent(s1, evFork, 0);
    k_Z    <<<BB*NNODE, 192, 0, s1>>>(x, Th);
    cudaEventRecord(evJoin, s1);

    // ---- main stream: attention chains ----
    k_prepVs<<<NNODE, 256>>>(Vs);
    k_lhs1 <<<dim3(BB, CCH), 192>>>(x, U1);
    k_rhsT <<<BB*NNODE/8, 256>>>(x, U3);
    k_lhs2 <<<BB*TTT, 256>>>(U2);
    k_prodT<<<BB, 576>>>();
    k_tAt  <<<BB, 576>>>(be, Ve);
    k_mega2<<<BB*NNODE/4, 256, MEGA_SMEM>>>(x, W1, W2, W3);
    k_prodS<<<dim3(32, 32, BB), 256>>>(bs);
    k_SgemmMMA<<<dim3(8, 8, BB), 256, 65536>>>();
    k_softS<<<dim3(16, BB), 256>>>();
    k_prepA<<<dim3(4, 96, BB), 256>>>(cheb);

    // join: gcnMMA needs Zh from side stream
    cudaStreamWaitEvent(0, evJoin, 0);
    k_gcnMMA<<<dim3(12, 8, BB), 256, 65536>>>();
    k_final<<<BB*NNODE/4, 256, 4*4632*4>>>(x, tw, tb, rw, rb, lg, lb, out);
}

// round 17
// speedup vs baseline: 1.1809x; 1.1809x over previous
#include <cuda_runtime.h>
#include <cuda_bf16.h>
#include <cuda_fp16.h>
#include <cstdint>

#define BB 32
#define NNODE 1024
#define CCH 64
#define TTT 24
#define CT 1536      // C*T == O*T == FT*T
#define K_GCN 3072   // plain fp16, K over (k,m)
#define K_SG  1024   // plain fp16, K over m

// ---------------- scratch (device globals; allocation-free) ----------------
__device__ float g_lhs1[BB*TTT*CCH];
__device__ float g_lhs2[BB*TTT*NNODE];
__device__ float g_rhsT[BB*NNODE*TTT];
__device__ float g_prodT[BB*TTT*TTT];
__device__ float g_tAt[BB*TTT*TTT];
__device__ float g_lhsB[BB*NNODE*TTT];
__device__ float g_rhsA[BB*NNODE*TTT];
__device__ float g_S[(size_t)BB*NNODE*NNODE];
__device__ __align__(16) uint32_t g_gcnH[(size_t)BB*NNODE*CT/2];    // half2 pairs
__device__ __align__(16) __half   g_Zh[(size_t)BB*K_GCN*CT];        // [b,km,ot] fp16
__device__ __align__(16) uint32_t g_sigH[(size_t)BB*NNODE*(K_SG/2)]; // [b,n,m/2]
__device__ __align__(16) uint32_t g_VsH[(size_t)NNODE*(K_SG/2)];     // [m,k/2]
__device__ __align__(16) uint32_t g_Ah[(size_t)BB*NNODE*(K_GCN/2)];  // [b,n,km/2]
__device__ __align__(16) uint32_t g_Bh[(size_t)BB*CT*(K_GCN/2)];     // [b,ot,km/2]

// ---------------- PTX helpers ----------------
__device__ __forceinline__ void cpa16(uint32_t dst, const void* src){
    asm volatile("cp.async.cg.shared.global [%0], [%1], 16;\n" :: "r"(dst), "l"(src));
}
__device__ __forceinline__ void cpa_commit(){ asm volatile("cp.async.commit_group;\n"); }
__device__ __forceinline__ void cpa_wait0(){ asm volatile("cp.async.wait_group 0;\n"); }
__device__ __forceinline__ void ldsm4(uint32_t* r, uint32_t addr){
    asm volatile("ldmatrix.sync.aligned.m8n8.x4.shared.b16 {%0,%1,%2,%3},[%4];"
        : "=r"(r[0]),"=r"(r[1]),"=r"(r[2]),"=r"(r[3]) : "r"(addr));
}
__device__ __forceinline__ void mma16816(float* c, const uint32_t* a, const uint32_t* b){
    asm volatile("mma.sync.aligned.m16n8k16.row.col.f32.f16.f16.f32 "
        "{%0,%1,%2,%3}, {%4,%5,%6,%7}, {%8,%9}, {%0,%1,%2,%3};"
        : "+f"(c[0]),"+f"(c[1]),"+f"(c[2]),"+f"(c[3])
        : "r"(a[0]),"r"(a[1]),"r"(a[2]),"r"(a[3]), "r"(b[0]),"r"(b[1]));
}
__device__ __forceinline__ uint32_t pack_ff(float a, float b){
    __half2 h = __floats2half2_rn(a, b);
    return *(uint32_t*)&h;
}

// ---------------- 1a: lhs1[b,t,c] = sum_n x[b,n,c,t]*U1[n] ----------------
__global__ void k_lhs1(const float* __restrict__ x, const float* __restrict__ U1){
    int b = blockIdx.x, c = blockIdx.y;
    int t = threadIdx.x % 24, r = threadIdx.x / 24;   // r in 0..7, blockDim 192
    float acc = 0.f;
    for(int n = r; n < NNODE; n += 8)
        acc += x[(((size_t)b*NNODE+n)*CCH+c)*TTT+t] * __ldg(U1+n);
    __shared__ float s[8][24];
    s[r][t] = acc;
    __syncthreads();
    if(r == 0){
        float v = 0.f;
        #pragma unroll
        for(int i = 0; i < 8; i++) v += s[i][t];
        g_lhs1[(b*TTT+t)*CCH+c] = v;
    }
}

// ---------------- 1c': rhsT[b,n,t] = sum_c U3[c]*x[b,n,c,t] ----------------
__global__ void k_rhsT(const float* __restrict__ x, const float* __restrict__ U3){
    int idx = blockIdx.x*8 + (threadIdx.x>>5);   // b*N+n
    int t = threadIdx.x & 31;
    if(t >= 24) return;
    size_t base = (size_t)idx*CT;
    float acc = 0.f;
    #pragma unroll
    for(int c = 0; c < CCH; c++) acc += __ldg(U3+c) * x[base + c*TTT + t];
    g_rhsT[idx*TTT + t] = acc;
}

// ---------------- 1b: lhs2[b,t,n] = sum_c lhs1[b,t,c]*U2[c,n] --------------
__global__ void k_lhs2(const float* __restrict__ U2){
    int bt = blockIdx.x;
    __shared__ float l[CCH];
    if(threadIdx.x < CCH) l[threadIdx.x] = g_lhs1[bt*CCH + threadIdx.x];
    __syncthreads();
    for(int n = threadIdx.x; n < NNODE; n += 256){
        float a = 0.f;
        #pragma unroll
        for(int c = 0; c < CCH; c++) a += l[c]*U2[c*NNODE + n];
        g_lhs2[bt*NNODE + n] = a;
    }
}

// ---------------- 1c: prodT[b,s,t] = sum_n lhs2[b,s,n]*rhsT[b,n,t] ---------
__global__ void k_prodT(){
    int b = blockIdx.x;
    int s = threadIdx.x / 24, t = threadIdx.x % 24;  // blockDim 576
    __shared__ float A[24][96], Bm[96][24];
    float acc = 0.f;
    for(int n0 = 0; n0 < NNODE; n0 += 96){
        __syncthreads();
        for(int i = threadIdx.x; i < 24*96; i += 576){
            int row = i/96, col = i%96;
            A[row][col] = g_lhs2[(b*TTT+row)*NNODE + n0 + col];
            int rr = i/24, cc = i%24;
            Bm[rr][cc] = g_rhsT[((size_t)b*NNODE + n0 + rr)*TTT + cc];
        }
        __syncthreads();
        #pragma unroll
        for(int j = 0; j < 96; j++) acc += A[s][j]*Bm[j][t];
    }
    g_prodT[(b*TTT+s)*TTT+t] = acc;
}

// ---------------- 1d: E = Ve @ sigmoid(prodT + be); softmax over axis s ----
__global__ void k_tAt(const float* __restrict__ be, const float* __restrict__ Ve){
    int b = blockIdx.x;
    int s = threadIdx.x / 24, y = threadIdx.x % 24;  // blockDim 576
    __shared__ float sig[24][24], E[24][25];
    __shared__ float mx[24], sm[24];
    float v = g_prodT[(b*TTT+s)*TTT+y] + __ldg(be + s*TTT + y);
    sig[s][y] = 1.f/(1.f + expf(-v));
    __syncthreads();
    float acc = 0.f;
    #pragma unroll
    for(int t = 0; t < 24; t++) acc += __ldg(Ve + s*TTT + t)*sig[t][y];
    E[s][y] = acc;
    __syncthreads();
    if(s == 0){
        float m = -1e30f;
        #pragma unroll
        for(int i = 0; i < 24; i++) m = fmaxf(m, E[i][y]);
        float ss = 0.f;
        #pragma unroll
        for(int i = 0; i < 24; i++) ss += expf(E[i][y]-m);
        mx[y] = m; sm[y] = ss;
    }
    __syncthreads();
    g_tAt[(b*TTT+s)*TTT+y] = expf(E[s][y]-mx[y])/sm[y];
}

// ---- 4 (tensor-core): Zh[b,km,ot] = fp16( Theta[ko,:]·x[bm,:,t] ) ---------
// Per bm: C[ko=192, t=24] = sum_c A[ko,c]·B[t,c]; M=192,N=24,K=64.
// Block: 256 thr = 2 bm-groups x 4 warps; 4 iterations => 8 bm per block.
__global__ void __launch_bounds__(256) k_Ztc(const float* __restrict__ x,
                                             const float* __restrict__ Theta){
    __shared__ __half shA[192*72];        // [ko][c], row stride 72
    __shared__ __half shB[2][24*72];      // [t][c],  row stride 72
    int tid = threadIdx.x;
    int wid = tid >> 5, lane = tid & 31;
    int grp = wid >> 2;                   // 0/1: which bm of the pair
    int widin = wid & 3;                  // warp within bm group

    // stage Theta once: shA[ko*72 + c] = fp16(Theta[k*4096 + c*64 + o])
    for(int idx = tid; idx < 192*64; idx += 256){
        int ko = idx >> 6, c = idx & 63;
        int k = ko >> 6, o = ko & 63;
        shA[ko*72 + c] = __float2half_rn(__ldg(Theta + k*4096 + c*64 + o));
    }
    __syncthreads();

    uint32_t aBase = (uint32_t)__cvta_generic_to_shared(shA);
    uint32_t bBase0 = (uint32_t)__cvta_generic_to_shared(&shB[grp][0]);

    for(int it = 0; it < 4; it++){
        size_t bm0 = (size_t)blockIdx.x*8 + it*2;
        // stage x for both bm of this iter: B[t][c] = fp16(x[bm, c, t])
        for(int i = tid; i < 2*1536; i += 256){
            int which = i >> 11;          // /2048? no: 1536*2=3072; use div
            int idx = i - which*1536;
            if(i >= 1536){ which = 1; idx = i - 1536; }
            else { which = 0; idx = i; }
            int c = idx / 24, t = idx - c*24;
            shB[which][t*72 + c] = __float2half_rn(x[(bm0+which)*CT + idx]);
        }
        __syncthreads();

        size_t bm = bm0 + grp;
        int b = (int)(bm >> 10), m = (int)(bm & 1023);

        float acc[3][3][4];
        #pragma unroll
        for(int mi = 0; mi < 3; mi++)
            #pragma unroll
            for(int ni = 0; ni < 3; ni++)
                #pragma unroll
                for(int q = 0; q < 4; q++) acc[mi][ni][q] = 0.f;

        #pragma unroll
        for(int j = 0; j < 4; j++){       // k16 steps over K=64
            // B frags: two ldsm4 loads
            uint32_t L1[4], L2[4];
            {
                int q = lane >> 3, r = lane & 7;
                uint32_t addr1 = bBase0 + (uint32_t)((((q>>1)*8 + r)*72 + (2*j + (q&1))*8)*2);
                ldsm4(L1, addr1);
                uint32_t addr2 = bBase0 + (uint32_t)(((16 + r)*72 + (2*j + (q&1))*8)*2);
                ldsm4(L2, addr2);
            }
            uint32_t bfr[3][2];
            bfr[0][0] = L1[0]; bfr[0][1] = L1[1];
            bfr[1][0] = L1[2]; bfr[1][1] = L1[3];
            bfr[2][0] = L2[0]; bfr[2][1] = L2[1];
            #pragma unroll
            for(int mi = 0; mi < 3; mi++){
                int wtile = widin*3 + mi;
                uint32_t a[4];
                uint32_t addr = aBase + (uint32_t)(((wtile*16 + (lane & 15))*72
                                         + (2*j + (lane>>4))*8)*2);
                ldsm4(a, addr);
                #pragma unroll
                for(int ni = 0; ni < 3; ni++)
                    mma16816(acc[mi][ni], a, bfr[ni]);
            }
        }

        // store: C[ko, t] -> Zh[(b*3+k)*1024+m][o*24+t]
        #pragma unroll
        for(int mi = 0; mi < 3; mi++){
            int wtile = widin*3 + mi;
            int r1 = wtile*16 + (lane >> 2);
            int r2 = r1 + 8;
            int k = r1 >> 6;              // same k for r1, r2 (16-aligned tiles)
            uint32_t* zrow = (uint32_t*)(g_Zh + (((size_t)(b*3 + k)<<10) + m)*CT);
            int o1 = r1 & 63, o2 = r2 & 63;
            #pragma unroll
            for(int ni = 0; ni < 3; ni++){
                int t = ni*8 + (lane & 3)*2;
                zrow[o1*12 + (t>>1)] = pack_ff(acc[mi][ni][0], acc[mi][ni][1]);
                zrow[o2*12 + (t>>1)] = pack_ff(acc[mi][ni][2], acc[mi][ni][3]);
            }
        }
        __syncthreads();
    }
}

// ------------- MEGA2: per (b,n) — x_TAt, lhsB, rhsA ------------------------
__global__ void __launch_bounds__(256) k_mega2(
        const float* __restrict__ x,
        const float* __restrict__ W1, const float* __restrict__ W2,
        const float* __restrict__ W3){
    extern __shared__ float sm[];
    float* a = sm;                        // 576: tAt[b]
    float* base = sm + 576;
    int grp = threadIdx.x >> 6, c = threadIdx.x & 63;  // 4 groups x 64
    float* xs  = base + grp*3136;         // 1536
    float* buf = xs + 1536;               // 64 x 25
    size_t bn = (size_t)blockIdx.x*4 + grp;
    int b = (int)(bn >> 10);

    for(int i = threadIdx.x; i < 576; i += 256) a[i] = g_tAt[b*576 + i];
    for(int i = c; i < 1536; i += 64) xs[i] = x[bn*CT + i];
    __syncthreads();

    float acc[24];
    #pragma unroll
    for(int s = 0; s < 24; s++) acc[s] = 0.f;
    const float* xr = xs + c*24;
    #pragma unroll 4
    for(int t = 0; t < 24; t++){
        float xv = xr[t];
        const float* ar = a + t*24;
        #pragma unroll
        for(int s = 0; s < 24; s++) acc[s] += xv*ar[s];
    }
    float la = 0.f;
    #pragma unroll
    for(int t = 0; t < 24; t++) la += acc[t]*__ldg(W1+t);

    float w3 = __ldg(W3 + c);
    #pragma unroll
    for(int t = 0; t < 24; t++) buf[c*25 + t] = w3*acc[t];
    __syncthreads();
    if(c < 24){
        float r = 0.f;
        #pragma unroll 8
        for(int c2 = 0; c2 < 64; c2++) r += buf[c2*25 + c];
        g_rhsA[bn*TTT + c] = r;
    }
    __syncthreads();
    #pragma unroll
    for(int t = 0; t < 24; t++) buf[c*25 + t] = la*__ldg(W2 + c*24 + t);
    __syncthreads();
    if(c < 24){
        float r = 0.f;
        #pragma unroll 8
        for(int c2 = 0; c2 < 64; c2++) r += buf[c2*25 + c];
        g_lhsB[bn*TTT + c] = r;
    }
}

// ----- 3d: sigH[b,n,m] = fp16 of sigmoid(lhsB·rhsAᵀ + bs) ------------------
__global__ void k_prodS(const float* __restrict__ bs){
    int b = blockIdx.z;
    int m0 = blockIdx.y*32, n0 = blockIdx.x*32;
    __shared__ float Am[32][25], Bn[32][25];
    __shared__ float st[32][33];   // [n local][m local]
    for(int i = threadIdx.x; i < 32*24; i += 256){
        int r = i/24, cc = i%24;
        Am[r][cc] = g_lhsB[((size_t)b*NNODE + m0 + r)*TTT + cc];
        Bn[r][cc] = g_rhsA[((size_t)b*NNODE + n0 + r)*TTT + cc];
    }
    __syncthreads();
    int tm = threadIdx.x >> 5, tn = threadIdx.x & 31;
    #pragma unroll
    for(int r = 0; r < 4; r++){
        int m = tm*4 + r;
        float acc = 0.f;
        #pragma unroll
        for(int t = 0; t < 24; t++) acc += Am[m][t]*Bn[tn][t];
        float v = acc + __ldg(bs + (size_t)(m0+m)*NNODE + n0 + tn);
        st[tn][m] = 1.f/(1.f + expf(-v));
    }
    __syncthreads();
    int nl = threadIdx.x >> 3, kq = (threadIdx.x & 7)*4;
    uint32_t* dst = g_sigH + ((size_t)(b*NNODE + n0 + nl))*(K_SG/2) + ((m0 + kq)>>1);
    uint2 w;
    w.x = pack_ff(st[nl][kq+0], st[nl][kq+1]);
    w.y = pack_ff(st[nl][kq+2], st[nl][kq+3]);
    *(uint2*)dst = w;
}

// ---------------- prep: VsH[m,k] = fp16 of Vs[m,k] -------------------------
__global__ void k_prepVs(const float* __restrict__ Vs){
    int m = blockIdx.x;
    for(int k2 = threadIdx.x; k2 < K_SG/2; k2 += 256){
        float v0 = Vs[(size_t)m*NNODE + 2*k2];
        float v1 = Vs[(size_t)m*NNODE + 2*k2 + 1];
        g_VsH[(size_t)m*(K_SG/2) + k2] = pack_ff(v0, v1);
    }
}

// ---------------- 3f: softmax over m of S (in place -> spatial_At) ---------
__global__ void k_softS(){
    int b = blockIdx.y;
    int ly = threadIdx.x & 63;
    int y = blockIdx.x*64 + ly;
    int tg = threadIdx.x >> 6;
    __shared__ float red[4][64];
    float* col = g_S + ((size_t)b<<20) + y;
    float m = -1e30f;
    for(int mm = tg; mm < NNODE; mm += 4) m = fmaxf(m, col[(size_t)mm*NNODE]);
    red[tg][ly] = m;
    __syncthreads();
    m = fmaxf(fmaxf(red[0][ly], red[1][ly]), fmaxf(red[2][ly], red[3][ly]));
    float s = 0.f;
    for(int mm = tg; mm < NNODE; mm += 4) s += expf(col[(size_t)mm*NNODE] - m);
    __syncthreads();
    red[tg][ly] = s;
    __syncthreads();
    s = red[0][ly] + red[1][ly] + red[2][ly] + red[3][ly];
    float inv = 1.f/s;
    for(int mm = tg; mm < NNODE; mm += 4){
        float v = col[(size_t)mm*NNODE];
        col[(size_t)mm*NNODE] = expf(v - m)*inv;
    }
}

// ----- prep A for gcn GEMM: Ah[b,n,km] = fp16(cheb[km,n]*At[b,m,n]) --------
__global__ void k_prepA(const float* __restrict__ cheb){
    int b = blockIdx.z, km0 = blockIdx.y*32, n0 = blockIdx.x*32;
    __shared__ float sm[32][33];
    int tid = threadIdx.x;
    int rr = tid>>5, cc = tid&31;
    #pragma unroll
    for(int i = 0; i < 4; i++){
        int kml = rr + i*8;
        int km = km0 + kml;
        int m = km & 1023;
        sm[kml][cc] = cheb[(size_t)km*NNODE + n0+cc]
                    * g_S[((size_t)b<<20) + ((size_t)m<<10) + n0+cc];
    }
    __syncthreads();
    int nl = tid>>3, kq = (tid&7)*4;
    uint32_t* dst = g_Ah + ((size_t)(b*NNODE + n0 + nl))*(K_GCN/2) + ((km0 + kq)>>1);
    uint2 w;
    w.x = pack_ff(sm[kq+0][nl], sm[kq+1][nl]);
    w.y = pack_ff(sm[kq+2][nl], sm[kq+3][nl]);
    *(uint2*)dst = w;
}

// ----- prep B for gcn GEMM: Bh[b,ot,km] = Zh[b,km,ot] (fp16 transpose) -----
__global__ void k_prepB(){
    int b = blockIdx.z, km0 = blockIdx.y*64, o0 = blockIdx.x*64;
    __shared__ uint32_t smT[64][33];   // [ot local][km-pair local]
    int tid = threadIdx.x;
    int j = tid >> 3;            // 0..31 km-pair
    int q = tid & 7;             // ot chunk of 8
    const uint32_t* r0 = (const uint32_t*)(g_Zh + ((size_t)b*3072 + km0 + 2*j    )*CT + o0) + q*4;
    const uint32_t* r1 = (const uint32_t*)(g_Zh + ((size_t)b*3072 + km0 + 2*j + 1)*CT + o0) + q*4;
    #pragma unroll
    for(int i = 0; i < 4; i++){
        uint32_t u0 = r0[i], u1 = r1[i];
        uint32_t w0, w1;
        asm("prmt.b32 %0, %1, %2, 0x5410;" : "=r"(w0) : "r"(u0), "r"(u1));
        asm("prmt.b32 %0, %1, %2, 0x7632;" : "=r"(w1) : "r"(u0), "r"(u1));
        smT[q*8 + i*2    ][j] = w0;
        smT[q*8 + i*2 + 1][j] = w1;
    }
    __syncthreads();
    int r = tid >> 2, c = (tid & 3)*8;
    uint32_t* dst = g_Bh + ((size_t)(b*CT + o0 + r))*(K_GCN/2) + (km0>>1) + c;
    uint4 v0, v1;
    v0.x = smT[r][c+0]; v0.y = smT[r][c+1]; v0.z = smT[r][c+2]; v0.w = smT[r][c+3];
    v1.x = smT[r][c+4]; v1.y = smT[r][c+5]; v1.z = smT[r][c+6]; v1.w = smT[r][c+7];
    *(uint4*)dst = v0; *(uint4*)(dst+4) = v1;
}

// ---------------- mma GEMM core: C[128,128] = A[128,K]·B[128,K]ᵀ -----------
template<bool RELU, bool HALF_OUT>
__device__ __forceinline__ void mma_core(const uint16_t* __restrict__ A,
                                         const uint16_t* __restrict__ B,
                                         void* __restrict__ C, int ldC, int KP){
    extern __shared__ uint16_t sh[];
    int m0 = blockIdx.y*128, n0 = blockIdx.x*128;
    const uint16_t* gA = A + (size_t)m0*KP;
    const uint16_t* gB = B + (size_t)n0*KP;
    int tid = threadIdx.x;
    int wid = tid>>5, lane = tid&31;
    int wm = (wid>>1)*32, wn = (wid&1)*64;
    uint32_t sA0 = (uint32_t)__cvta_generic_to_shared(sh);
    uint32_t sB0 = sA0 + 2*16384;

    float acc[2][8][4];
    #pragma unroll
    for(int mi = 0; mi < 2; mi++)
        #pragma unroll
        for(int ni = 0; ni < 8; ni++)
            #pragma unroll
            for(int q = 0; q < 4; q++) acc[mi][ni][q] = 0.f;

    auto loadStage = [&](int buf, int k0){
        #pragma unroll
        for(int i = 0; i < 4; i++){
            int idx = tid + i*256;
            int row = idx>>3, cc = idx&7;
            int pc = (cc ^ (row & 7));
            cpa16(sA0 + (uint32_t)(buf*16384 + (row*64 + pc*8)*2),
                  gA + (size_t)row*KP + k0 + cc*8);
            cpa16(sB0 + (uint32_t)(buf*16384 + (row*64 + pc*8)*2),
                  gB + (size_t)row*KP + k0 + cc*8);
        }
        cpa_commit();
    };

    int ns = KP/64;
    loadStage(0, 0);
    cpa_wait0();
    __syncthreads();
    for(int s = 0; s < ns; s++){
        int buf = s & 1;
        if(s + 1 < ns) loadStage(buf^1, (s+1)*64);
        uint32_t baseA = sA0 + buf*16384;
        uint32_t baseB = sB0 + buf*16384;
        #pragma unroll
        for(int j = 0; j < 4; j++){
            uint32_t a[2][4];
            int arow = wm + (lane & 15);
            int acc_ = 2*j + (lane >> 4);
            #pragma unroll
            for(int mi = 0; mi < 2; mi++){
                int r = arow + mi*16;
                ldsm4(a[mi], baseA + (uint32_t)((r*64 + ((acc_ ^ (r&7))*8))*2));
            }
            uint32_t bb[4][4];
            int brow = wn + (lane & 7) + ((lane >> 4) << 3);
            int bcc = 2*j + ((lane >> 3) & 1);
            #pragma unroll
            for(int p = 0; p < 4; p++){
                int r = brow + p*16;
                ldsm4(bb[p], baseB + (uint32_t)((r*64 + ((bcc ^ (r&7))*8))*2));
            }
            #pragma unroll
            for(int mi = 0; mi < 2; mi++)
                #pragma unroll
                for(int ni = 0; ni < 8; ni++)
                    mma16816(acc[mi][ni], a[mi], &bb[ni>>1][(ni&1)*2]);
        }
        if(s + 1 < ns) cpa_wait0();
        __syncthreads();
    }

    int r0 = m0 + wm + (lane >> 2);
    int c0 = n0 + wn + (lane & 3)*2;
    #pragma unroll
    for(int mi = 0; mi < 2; mi++){
        #pragma unroll
        for(int ni = 0; ni < 8; ni++){
            float v0 = acc[mi][ni][0], v1 = acc[mi][ni][1];
            float v2 = acc[mi][ni][2], v3 = acc[mi][ni][3];
            if(RELU){
                v0 = fmaxf(v0,0.f); v1 = fmaxf(v1,0.f);
                v2 = fmaxf(v2,0.f); v3 = fmaxf(v3,0.f);
            }
            int r = r0 + mi*16, c = c0 + ni*8;
            if(HALF_OUT){
                uint32_t* Ch = (uint32_t*)C;
                Ch[(size_t)r*ldC + (c>>1)]     = pack_ff(v0, v1);
                Ch[(size_t)(r+8)*ldC + (c>>1)] = pack_ff(v2, v3);
            }else{
                float* Cf = (float*)C;
                float2 w0; w0.x = v0; w0.y = v1;
                float2 w1; w1.x = v2; w1.y = v3;
                *(float2*)(Cf + (size_t)r*ldC + c)     = w0;
                *(float2*)(Cf + (size_t)(r+8)*ldC + c) = w1;
            }
        }
    }
}

// 3e: S[b] = Vs @ sig[b]  (plain fp16)
__global__ void __launch_bounds__(256,2) k_SgemmMMA(){
    int b = blockIdx.z;
    mma_core<false,false>((const uint16_t*)g_VsH,
                          (const uint16_t*)(g_sigH + (size_t)b*NNODE*(K_SG/2)),
                          g_S + ((size_t)b<<20), NNODE, K_SG);
}
// 5: gcnH[b] = relu( A·Bᵀ )  (plain fp16, half2-packed output)
__global__ void __launch_bounds__(256,2) k_gcnMMA(){
    int b = blockIdx.z;
    mma_core<true,true>((const uint16_t*)(g_Ah + (size_t)b*NNODE*(K_GCN/2)),
                        (const uint16_t*)(g_Bh + (size_t)b*CT*(K_GCN/2)),
                        g_gcnH + (size_t)b*NNODE*(CT/2), CT/2, K_GCN);
}

// ------- 6: tconv + rconv + relu + LN(ft) + transpose -> out ---------------
__global__ void k_final(const float* __restrict__ x,
                        const float* __restrict__ twg, const float* __restrict__ tbg,
                        const float* __restrict__ rwg, const float* __restrict__ rbg,
                        const float* __restrict__ lng, const float* __restrict__ lnb,
                        float* __restrict__ out){
    extern __shared__ float smdyn[];
    int grp = threadIdx.x >> 6;           // blockDim 256 = 4 groups x 64
    int ft  = threadIdx.x & 63;
    size_t bn = (size_t)blockIdx.x*4 + grp;
    float* xs = smdyn + grp*4632;
    float* gs = xs + 1536;
    float* ys = gs + 1536;                // stride 65 per t: 24*65 = 1560
    __shared__ float s_mu[4][24], s_rs[4][24];
    for(int i = ft; i < 1536; i += 64) xs[i] = x[bn*CT + i];
    const uint32_t* gh = g_gcnH + bn*(CT/2);
    for(int ii = ft; ii < CT/2; ii += 64){
        uint32_t u = gh[ii];
        __half2 h = *(__half2*)&u;
        float2 f = __half22float2(h);
        gs[ii*2]   = f.x;
        gs[ii*2+1] = f.y;
    }
    __syncthreads();
    float acc[24];
    float bias = __ldg(tbg+ft) + __ldg(rbg+ft);
    #pragma unroll
    for(int t = 0; t < 24; t++) acc[t] = bias;
    const float* rwr = rwg + ft*64;
    #pragma unroll 4
    for(int c = 0; c < 64; c++){
        float w = __ldg(rwr + c);
        const float* xr = xs + c*24;
        #pragma unroll
        for(int t = 0; t < 24; t++) acc[t] += w*xr[t];
    }
    const float* twr = twg + ft*192;
    #pragma unroll 2
    for(int o = 0; o < 64; o++){
        float w0 = __ldg(twr + o*3), w1 = __ldg(twr + o*3 + 1), w2 = __ldg(twr + o*3 + 2);
        const float* gr = gs + o*24;
        #pragma unroll
        for(int t = 0; t < 24; t++){
            float s = w1*gr[t];
            if(t > 0)  s += w0*gr[t-1];
            if(t < 23) s += w2*gr[t+1];
            acc[t] += s;
        }
    }
    #pragma unroll
    for(int t = 0; t < 24; t++) ys[t*65 + ft] = fmaxf(acc[t], 0.f);
    __syncthreads();
    int lane = threadIdx.x & 31;
    int wg = ft >> 5;
    for(int t = wg; t < 24; t += 2){
        float v1 = ys[t*65 + lane], v2 = ys[t*65 + 32 + lane];
        float s = v1 + v2, q = v1*v1 + v2*v2;
        #pragma unroll
        for(int off = 16; off; off >>= 1){
            s += __shfl_xor_sync(0xffffffffu, s, off);
            q += __shfl_xor_sync(0xffffffffu, q, off);
        }
        if(lane == 0){
            float mean = s*(1.f/64.f);
            s_mu[grp][t] = mean;
            s_rs[grp][t] = rsqrtf(q*(1.f/64.f) - mean*mean + 1e-5f);
        }
    }
    __syncthreads();
    float gg = __ldg(lng+ft), bv = __ldg(lnb+ft);
    #pragma unroll
    for(int t = 0; t < 24; t++)
        ys[t*65 + ft] = (ys[t*65 + ft] - s_mu[grp][t])*s_rs[grp][t]*gg + bv;
    __syncthreads();
    for(int i = ft; i < 1536; i += 64)
        out[bn*CT + i] = ys[(i%24)*65 + (i/24)];
}

// ---------------------------------------------------------------------------
extern "C" void kernel_launch(void* const* d_in, const int* in_sizes, int n_in,
                              void* d_out, int out_size){
    const float* x   = (const float*)d_in[0];
    const float* W1  = (const float*)d_in[1];
    const float* W2  = (const float*)d_in[2];
    const float* W3  = (const float*)d_in[3];
    const float* bs  = (const float*)d_in[4];
    const float* Vs  = (const float*)d_in[5];
    const float* U1  = (const float*)d_in[6];
    const float* U2  = (const float*)d_in[7];
    const float* U3  = (const float*)d_in[8];
    const float* be  = (const float*)d_in[9];
    const float* Ve  = (const float*)d_in[10];
    const float* Th  = (const float*)d_in[11];
    const float* cheb= (const float*)d_in[12];
    const float* tw  = (const float*)d_in[13];
    const float* tb  = (const float*)d_in[14];
    const float* rw  = (const float*)d_in[15];
    const float* rb  = (const float*)d_in[16];
    const float* lg  = (const float*)d_in[17];
    const float* lb  = (const float*)d_in[18];
    float* out = (float*)d_out;

    static cudaStream_t s1 = nullptr;
    static cudaEvent_t evFork = nullptr, evJoin = nullptr;
    if(s1 == nullptr){
        cudaStreamCreateWithFlags(&s1, cudaStreamNonBlocking);
        cudaEventCreateWithFlags(&evFork, cudaEventDisableTiming);
        cudaEventCreateWithFlags(&evJoin, cudaEventDisableTiming);
    }

    const int MEGA_SMEM = (576 + 4*3136)*4;   // 52480 B
    cudaFuncSetAttribute(k_final, cudaFuncAttributeMaxDynamicSharedMemorySize, 4*4632*4);
    cudaFuncSetAttribute(k_mega2, cudaFuncAttributeMaxDynamicSharedMemorySize, MEGA_SMEM);
    cudaFuncSetAttribute(k_SgemmMMA, cudaFuncAttributeMaxDynamicSharedMemorySize, 65536);
    cudaFuncSetAttribute(k_gcnMMA,   cudaFuncAttributeMaxDynamicSharedMemorySize, 65536);

    // ---- fork side stream: Z (tensor-core) -> prepB ----
    cudaEventRecord(evFork, 0);
    cudaStreamWaitEvent(s1, evFork, 0);
    k_Ztc  <<<BB*NNODE/8, 256, 0, s1>>>(x, Th);
    k_prepB<<<dim3(24, 48, BB), 256, 0, s1>>>();
    cudaEventRecord(evJoin, s1);

    // ---- main stream: attention chains ----
    k_prepVs<<<NNODE, 256>>>(Vs);
    k_lhs1 <<<dim3(BB, CCH), 192>>>(x, U1);
    k_rhsT <<<BB*NNODE/8, 256>>>(x, U3);
    k_lhs2 <<<BB*TTT, 256>>>(U2);
    k_prodT<<<BB, 576>>>();
    k_tAt  <<<BB, 576>>>(be, Ve);
    k_mega2<<<BB*NNODE/4, 256, MEGA_SMEM>>>(x, W1, W2, W3);
    k_prodS<<<dim3(32, 32, BB), 256>>>(bs);
    k_SgemmMMA<<<dim3(8, 8, BB), 256, 65536>>>();
    k_softS<<<dim3(16, BB), 256>>>();
    k_prepA<<<dim3(32, 96, BB), 256>>>(cheb);

    // join: gcnMMA needs Bh from side stream
    cudaStreamWaitEvent(0, evJoin, 0);
    k_gcnMMA<<<dim3(12, 8, BB), 256, 65536>>>();
    k_final<<<BB*NNODE/4, 256, 4*4632*4>>>(x, tw, tb, rw, rb, lg, lb, out);
}